// round 15
// baseline (speedup 1.0000x reference)
#include <cuda_runtime.h>
#include <cstdint>

#define BB 8192
#define LL 200
#define QQ 128
#define HH 128
#define GRID 148
#define NTHREADS 512
#define NWARPS 16

#define ROW_FLOATS (LL * HH)          // 25600
#define ROW_BYTES  (ROW_FLOATS * 4)   // 102400

// ---------------------------------------------------------------------------
// PTX helpers
// ---------------------------------------------------------------------------
__device__ __forceinline__ uint32_t smem_u32(const void* p) {
    uint32_t a;
    asm("{ .reg .u64 t; cvta.to.shared.u64 t, %1; cvt.u32.u64 %0, t; }"
        : "=r"(a) : "l"(p));
    return a;
}
__device__ __forceinline__ void mbar_init(uint32_t mbar, uint32_t count) {
    asm volatile("mbarrier.init.shared.b64 [%0], %1;" :: "r"(mbar), "r"(count) : "memory");
}
__device__ __forceinline__ void mbar_expect_tx(uint32_t mbar, uint32_t bytes) {
    asm volatile("mbarrier.arrive.expect_tx.shared.b64 _, [%0], %1;"
                 :: "r"(mbar), "r"(bytes) : "memory");
}
__device__ __forceinline__ void bulk_g2s(uint32_t dst, const void* src,
                                         uint32_t bytes, uint32_t mbar) {
    asm volatile(
        "cp.async.bulk.shared::cta.global.mbarrier::complete_tx::bytes "
        "[%0], [%1], %2, [%3];"
        :: "r"(dst), "l"(src), "r"(bytes), "r"(mbar) : "memory");
}
__device__ __forceinline__ void mbar_wait(uint32_t mbar, uint32_t parity) {
    uint32_t done;
    asm volatile(
        "{\n .reg .pred p;\n"
        " mbarrier.try_wait.parity.acquire.cta.shared::cta.b64 p, [%1], %2, 0x989680;\n"
        " selp.b32 %0, 1, 0, p;\n}"
        : "=r"(done) : "r"(mbar), "r"(parity) : "memory");
    while (!done) {
        asm volatile(
            "{\n .reg .pred p;\n"
            " mbarrier.try_wait.parity.acquire.cta.shared::cta.b64 p, [%1], %2, 0x989680;\n"
            " selp.b32 %0, 1, 0, p;\n}"
            : "=r"(done) : "r"(mbar), "r"(parity) : "memory");
    }
}

// ---------------------------------------------------------------------------
// Single persistent kernel. grid=148 (1 CTA/SM), 512 threads (16 warps,
// 128-reg cap -> W slice fits in registers, no spills).
//
// Each thread permanently holds W[qc*32 .. qc*32+31][h] in 32 registers
// (h = tid&127, qc = tid>>7). Per row, qw[b] = q_b @ W is recomputed on the
// fly (32 broadcast LDS + 32 FMA + SMEM 4-way reduce) inside the
// memory-bound streaming loop — absorbed by its ~22% compute slack.
//
// SMEM (floats):
//   buf0 [0,25600) | buf1 [25600,51200)
//   s_qb  [51200,51328)   staged query row
//   s_qw  [51328,51456)   qw for current row
//   s_tmp [51456,51968)   4x128 qw partials
//   s_logits [51968,52224)
//   s_red [52224,52256) | s_flag @52256
//   s_part [52260,54308) (16x128)
//   mbar (2 x u64) @ 54308
// ---------------------------------------------------------------------------
__global__ __launch_bounds__(NTHREADS, 1) void attn_fused_kernel(
    const float* __restrict__ query, const float* __restrict__ W,
    const float* __restrict__ hist,  const void* __restrict__ hlen,
    float* __restrict__ out)
{
    extern __shared__ float smem[];
    float*  bufs[2] = { smem, smem + ROW_FLOATS };
    float*  s_qb     = smem + 2 * ROW_FLOATS;          // 51200
    float*  s_qw     = s_qb + 128;                     // 51328
    float*  s_tmp    = s_qw + 128;                     // 51456 (4x128)
    float*  s_logits = s_tmp + 512;                    // 51968
    float*  s_red    = s_logits + 256;                 // 52224
    int*    s_flag   = (int*)(s_red + 32);             // 52256
    float*  s_part   = s_red + 36;                     // 52260 (16x128)
    uint64_t* mbar   = (uint64_t*)(smem + 54308);      // byte 217232, 8B aligned

    const int tid  = threadIdx.x;
    const int warp = tid >> 5;
    const int lane = tid & 31;
    const int bid  = blockIdx.x;
    const int k    = lane & 7;      // column octet (0..7)
    const int r    = lane >> 3;     // row-in-group (0..3)
    const int h    = tid & 127;     // W column owned by this thread
    const int qc   = tid >> 7;      // W q-chunk (0..3)

    const uint32_t m0 = smem_u32(&mbar[0]);
    const uint32_t m1 = smem_u32(&mbar[1]);
    const uint32_t buf_a[2] = { smem_u32(bufs[0]), smem_u32(bufs[1]) };

    if (tid == 0) { mbar_init(m0, 1); mbar_init(m1, 1); }
    __syncthreads();

    // ---- prologue ----
    if (tid == 0) {
        mbar_expect_tx(m0, ROW_BYTES);
        bulk_g2s(buf_a[0], hist + (size_t)bid * ROW_FLOATS, ROW_BYTES, m0);
        // length dtype: int64 values in [0,200) -> all odd dwords zero
        const int* len32 = (const int*)hlen;
        int nz = 0;
#pragma unroll
        for (int i = 1; i < 256; i += 2) nz += (len32[i] != 0);
        *s_flag = (nz == 0) ? 1 : 0;
    }

    // W slice into registers: wreg[i] = W[qc*32+i][h]  (coalesced LDG)
    float wreg[32];
    {
        const float* wp = W + (size_t)(qc * 32) * HH + h;
#pragma unroll
        for (int i = 0; i < 32; ++i) wreg[i] = wp[i * HH];
    }
    __syncthreads();
    const int is64 = *s_flag;

    // ---- main loop ----
    uint32_t ph0 = 0, ph1 = 0;
    int it = 0;
    for (int b = bid; b < BB; b += GRID, ++it) {
        const int cur = it & 1;

        // prefetch next row into the other buffer (consumed last iteration)
        const int bn = b + GRID;
        if (bn < BB && tid == 0) {
            const uint32_t mb = cur ? m0 : m1;
            mbar_expect_tx(mb, ROW_BYTES);
            bulk_g2s(buf_a[cur ^ 1], hist + (size_t)bn * ROW_FLOATS, ROW_BYTES, mb);
        }

        // stage q_b (warp 0, one LDG.128/lane)
        if (warp == 0)
            ((float4*)s_qb)[lane] = ((const float4*)query)[(size_t)b * 32 + lane];

        int Lb;
        if (is64) Lb = (int)((const long long*)hlen)[b];
        else      Lb = ((const int*)hlen)[b];
        const int g0 = Lb >> 2;      // first group with any unmasked row

        __syncthreads();             // s_qb visible (barrier A)

        // qw partials: 32 broadcast LDS + 32 FMA against the register W slice
        {
            const float* qb = s_qb + qc * 32;
            float p0 = 0.f, p1 = 0.f, p2 = 0.f, p3 = 0.f;
#pragma unroll
            for (int i = 0; i < 32; i += 4) {
                p0 = fmaf(wreg[i],     qb[i],     p0);
                p1 = fmaf(wreg[i + 1], qb[i + 1], p1);
                p2 = fmaf(wreg[i + 2], qb[i + 2], p2);
                p3 = fmaf(wreg[i + 3], qb[i + 3], p3);
            }
            s_tmp[qc * 128 + h] = (p0 + p1) + (p2 + p3);
        }
        __syncthreads();             // s_tmp complete (barrier B)
        if (tid < HH)
            s_qw[tid] = (s_tmp[tid] + s_tmp[128 + tid]) +
                        (s_tmp[256 + tid] + s_tmp[384 + tid]);

        // wait current buffer (all threads), then barrier C makes s_qw visible
        if (cur == 0) { mbar_wait(m0, ph0); ph0 ^= 1; }
        else          { mbar_wait(m1, ph1); ph1 ^= 1; }
        __syncthreads();             // barrier C: s_qw + TMA buffer ready

        const float4* s4  = (const float4*)bufs[cur];
        const float4* qw4 = (const float4*)s_qw;
        float4 qv[4];
#pragma unroll
        for (int c = 0; c < 4; ++c) qv[c] = qw4[c * 8 + k];

        // ---- pass 1: e_l = exp(logit_l) for l >= Lb only; masked groups
        // skipped entirely, active groups rebalanced across warps.
        float wsum = 0.f;
        for (int g = g0 + warp; g < 50; g += NWARPS) {
            const int l = g * 4 + r;
            const float4* row4 = s4 + l * 32;
            float p = 0.f;
#pragma unroll
            for (int c = 0; c < 4; ++c) {
                float4 v = row4[c * 8 + k];
                p += v.x * qv[c].x + v.y * qv[c].y + v.z * qv[c].z + v.w * qv[c].w;
            }
            p += __shfl_xor_sync(0xffffffffu, p, 4);
            p += __shfl_xor_sync(0xffffffffu, p, 2);
            p += __shfl_xor_sync(0xffffffffu, p, 1);
            float e = 0.f;
            if (l >= Lb) e = __expf(p);        // boundary-group masked lanes: 0
            if (k == 0) { s_logits[l] = e; wsum += e; }
        }
        // combine k==0 lanes (0,8,16,24)
        wsum += __shfl_xor_sync(0xffffffffu, wsum, 16);
        wsum += __shfl_xor_sync(0xffffffffu, wsum, 8);
        if (lane == 0) s_red[warp] = wsum;
        __syncthreads();             // barrier D

        // private 1/tot: masked rows contribute exactly 1.0 each (exp(1e-9))
        float t0 = 0.f, t1 = 0.f, t2 = 0.f, t3 = 0.f;
#pragma unroll
        for (int w = 0; w < NWARPS; w += 4) {
            t0 += s_red[w]; t1 += s_red[w + 1]; t2 += s_red[w + 2]; t3 += s_red[w + 3];
        }
        const float inv = __frcp_rn((float)Lb + ((t0 + t1) + (t2 + t3)));

        // ---- pass 2: out[h] = inv * sum_l w_l * hist[l][h] (SMEM only) ----
        float4 a4 = {0.f, 0.f, 0.f, 0.f};
        for (int l = warp; l < LL; l += NWARPS) {
            const float sc = (l < Lb) ? 1.0f : s_logits[l];
            float4 v = s4[l * 32 + lane];
            a4.x = fmaf(sc, v.x, a4.x);
            a4.y = fmaf(sc, v.y, a4.y);
            a4.z = fmaf(sc, v.z, a4.z);
            a4.w = fmaf(sc, v.w, a4.w);
        }
        a4.x *= inv; a4.y *= inv; a4.z *= inv; a4.w *= inv;
        ((float4*)s_part)[warp * 32 + lane] = a4;
        __syncthreads();             // barrier E: all buf[cur] reads done

        // ---- final reduce: 128 threads, conflict-free scalar columns ----
        if (tid < HH) {
            float vsum = 0.f;
#pragma unroll
            for (int g = 0; g < NWARPS; ++g) vsum += s_part[g * HH + tid];
            out[(size_t)b * HH + tid] = vsum;
        }
    }
}

// ---------------------------------------------------------------------------
extern "C" void kernel_launch(void* const* d_in, const int* in_sizes, int n_in,
                              void* d_out, int out_size) {
    // Bind inputs BY ELEMENT COUNT (all distinct) — immune to ordering.
    const float* query = nullptr;   // 1048576
    const float* hist  = nullptr;   // 209715200
    const void*  hlen  = nullptr;   // 8192
    const float* W     = nullptr;   // 16384
    for (int i = 0; i < n_in; ++i) {
        switch (in_sizes[i]) {
            case BB * QQ:      query = (const float*)d_in[i]; break;
            case BB * LL * HH: hist  = (const float*)d_in[i]; break;
            case BB:           hlen  = d_in[i];               break;
            case QQ * HH:      W     = (const float*)d_in[i]; break;
            default: break;
        }
    }
    float* out = (float*)d_out;

    const int smem = 54308 * 4 + 64;   // 217296 B

    cudaFuncSetAttribute(attn_fused_kernel,
                         cudaFuncAttributeMaxDynamicSharedMemorySize, smem);

    attn_fused_kernel<<<GRID, NTHREADS, smem>>>(query, W, hist, hlen, out);
}

// round 16
// speedup vs baseline: 1.0154x; 1.0154x over previous
#include <cuda_runtime.h>
#include <cstdint>

#define BB 8192
#define LL 200
#define QQ 128
#define HH 128
#define GRID 148
#define NTHREADS 512
#define NWARPS 16

#define ROW_FLOATS (LL * HH)          // 25600
#define ROW_BYTES  (ROW_FLOATS * 4)   // 102400

// ---------------------------------------------------------------------------
// PTX helpers
// ---------------------------------------------------------------------------
__device__ __forceinline__ uint32_t smem_u32(const void* p) {
    uint32_t a;
    asm("{ .reg .u64 t; cvta.to.shared.u64 t, %1; cvt.u32.u64 %0, t; }"
        : "=r"(a) : "l"(p));
    return a;
}
__device__ __forceinline__ void mbar_init(uint32_t mbar, uint32_t count) {
    asm volatile("mbarrier.init.shared.b64 [%0], %1;" :: "r"(mbar), "r"(count) : "memory");
}
__device__ __forceinline__ void mbar_expect_tx(uint32_t mbar, uint32_t bytes) {
    asm volatile("mbarrier.arrive.expect_tx.shared.b64 _, [%0], %1;"
                 :: "r"(mbar), "r"(bytes) : "memory");
}
__device__ __forceinline__ void bulk_g2s(uint32_t dst, const void* src,
                                         uint32_t bytes, uint32_t mbar) {
    asm volatile(
        "cp.async.bulk.shared::cta.global.mbarrier::complete_tx::bytes "
        "[%0], [%1], %2, [%3];"
        :: "r"(dst), "l"(src), "r"(bytes), "r"(mbar) : "memory");
}
__device__ __forceinline__ void mbar_wait(uint32_t mbar, uint32_t parity) {
    uint32_t done;
    asm volatile(
        "{\n .reg .pred p;\n"
        " mbarrier.try_wait.parity.acquire.cta.shared::cta.b64 p, [%1], %2, 0x989680;\n"
        " selp.b32 %0, 1, 0, p;\n}"
        : "=r"(done) : "r"(mbar), "r"(parity) : "memory");
    while (!done) {
        asm volatile(
            "{\n .reg .pred p;\n"
            " mbarrier.try_wait.parity.acquire.cta.shared::cta.b64 p, [%1], %2, 0x989680;\n"
            " selp.b32 %0, 1, 0, p;\n}"
            : "=r"(done) : "r"(mbar), "r"(parity) : "memory");
    }
}

// ---------------------------------------------------------------------------
// Single persistent kernel. grid=148 (1 CTA/SM), 512 threads (16 warps).
//
// W lives in registers (32 floats/thread: h = tid&127, qc = tid>>7).
// qw[b+1] is software-pipelined: partial dot computed between the loop's
// existing barriers D and E (inside the memory-bound slack window); the
// 4-way reduce happens at loop top, sealed by ONE added barrier (T).
// Pass-1/pass-2 identical to the 138.5us-measured structure.
//
// SMEM (floats):
//   buf0 [0,25600) | buf1 [25600,51200)
//   s_qb [51200,51328) | s_qw [51328,51456) | s_tmp [51456,51968)
//   s_logits [51968,52224) | s_red [52224,52256) | s_flag @52256
//   s_part [52260,54308) | mbar (2 x u64) @ 54308
// ---------------------------------------------------------------------------
__global__ __launch_bounds__(NTHREADS, 1) void attn_fused_kernel(
    const float* __restrict__ query, const float* __restrict__ W,
    const float* __restrict__ hist,  const void* __restrict__ hlen,
    float* __restrict__ out)
{
    extern __shared__ float smem[];
    float*  bufs[2] = { smem, smem + ROW_FLOATS };
    float*  s_qb     = smem + 2 * ROW_FLOATS;          // 51200
    float*  s_qw     = s_qb + 128;                     // 51328
    float*  s_tmp    = s_qw + 128;                     // 51456 (4x128)
    float*  s_logits = s_tmp + 512;                    // 51968
    float*  s_red    = s_logits + 256;                 // 52224
    int*    s_flag   = (int*)(s_red + 32);             // 52256
    float*  s_part   = s_red + 36;                     // 52260 (16x128)
    uint64_t* mbar   = (uint64_t*)(smem + 54308);      // byte 217232, 8B aligned

    const int tid  = threadIdx.x;
    const int warp = tid >> 5;
    const int lane = tid & 31;
    const int bid  = blockIdx.x;
    const int k    = lane & 7;      // column octet (0..7)
    const int r    = lane >> 3;     // row-in-group (0..3)
    const int h    = tid & 127;     // W column owned by this thread
    const int qc   = tid >> 7;      // W q-chunk (0..3)

    const uint32_t m0 = smem_u32(&mbar[0]);
    const uint32_t m1 = smem_u32(&mbar[1]);
    const uint32_t buf_a[2] = { smem_u32(bufs[0]), smem_u32(bufs[1]) };

    if (tid == 0) { mbar_init(m0, 1); mbar_init(m1, 1); }
    __syncthreads();

    // ---- prologue ----
    if (tid == 0) {
        mbar_expect_tx(m0, ROW_BYTES);
        bulk_g2s(buf_a[0], hist + (size_t)bid * ROW_FLOATS, ROW_BYTES, m0);
        // length dtype: int64 values in [0,200) -> all odd dwords zero
        const int* len32 = (const int*)hlen;
        int nz = 0;
#pragma unroll
        for (int i = 1; i < 256; i += 2) nz += (len32[i] != 0);
        *s_flag = (nz == 0) ? 1 : 0;
    }

    // W slice into registers: wreg[i] = W[qc*32+i][h]  (coalesced LDG)
    float wreg[32];
    {
        const float* wp = W + (size_t)(qc * 32) * HH + h;
#pragma unroll
        for (int i = 0; i < 32; ++i) wreg[i] = wp[i * HH];
    }
    // stage q[bid]
    if (warp == 0)
        ((float4*)s_qb)[lane] = ((const float4*)query)[(size_t)bid * 32 + lane];
    __syncthreads();                  // s_qb + s_flag visible
    const int is64 = *s_flag;

    // iteration-0 qw partials -> s_tmp (loop-top reduce finishes it)
    {
        const float* qb = s_qb + qc * 32;
        float p0 = 0.f, p1 = 0.f, p2 = 0.f, p3 = 0.f;
#pragma unroll
        for (int i = 0; i < 32; i += 4) {
            p0 = fmaf(wreg[i],     qb[i],     p0);
            p1 = fmaf(wreg[i + 1], qb[i + 1], p1);
            p2 = fmaf(wreg[i + 2], qb[i + 2], p2);
            p3 = fmaf(wreg[i + 3], qb[i + 3], p3);
        }
        s_tmp[qc * 128 + h] = (p0 + p1) + (p2 + p3);
    }
    __syncthreads();                  // s_tmp visible for the first loop-top reduce

    // ---- main loop ----
    uint32_t ph0 = 0, ph1 = 0;
    int it = 0;
    for (int b = bid; b < BB; b += GRID, ++it) {
        const int cur = it & 1;
        const int bn  = b + GRID;

        // loop top: finish qw[b] (partials guaranteed by prologue / barrier E)
        if (tid < HH)
            s_qw[tid] = (s_tmp[tid] + s_tmp[128 + tid]) +
                        (s_tmp[256 + tid] + s_tmp[384 + tid]);

        // issue next row TMA + stage q[b+GRID] (visibility sealed by barrier D)
        if (bn < BB) {
            if (tid == 0) {
                const uint32_t mb = cur ? m0 : m1;
                mbar_expect_tx(mb, ROW_BYTES);
                bulk_g2s(buf_a[cur ^ 1], hist + (size_t)bn * ROW_FLOATS, ROW_BYTES, mb);
            }
            if (warp == 0)
                ((float4*)s_qb)[lane] = ((const float4*)query)[(size_t)bn * 32 + lane];
        }

        int Lb;
        if (is64) Lb = (int)((const long long*)hlen)[b];
        else      Lb = ((const int*)hlen)[b];
        const int g0 = Lb >> 2;       // first group with any unmasked row

        __syncthreads();              // barrier T: s_qw[b] visible

        // wait current buffer
        if (cur == 0) { mbar_wait(m0, ph0); ph0 ^= 1; }
        else          { mbar_wait(m1, ph1); ph1 ^= 1; }

        const float4* s4  = (const float4*)bufs[cur];
        const float4* qw4 = (const float4*)s_qw;
        float4 qv[4];
#pragma unroll
        for (int c = 0; c < 4; ++c) qv[c] = qw4[c * 8 + k];

        // ---- pass 1: e_l = exp(logit_l) for l >= Lb only; masked groups
        // skipped entirely, active groups rebalanced across warps.
        float wsum = 0.f;
        for (int g = g0 + warp; g < 50; g += NWARPS) {
            const int l = g * 4 + r;
            const float4* row4 = s4 + l * 32;
            float p = 0.f;
#pragma unroll
            for (int c = 0; c < 4; ++c) {
                float4 v = row4[c * 8 + k];
                p += v.x * qv[c].x + v.y * qv[c].y + v.z * qv[c].z + v.w * qv[c].w;
            }
            p += __shfl_xor_sync(0xffffffffu, p, 4);
            p += __shfl_xor_sync(0xffffffffu, p, 2);
            p += __shfl_xor_sync(0xffffffffu, p, 1);
            float e = 0.f;
            if (l >= Lb) e = __expf(p);        // boundary-group masked lanes: 0
            if (k == 0) { s_logits[l] = e; wsum += e; }
        }
        wsum += __shfl_xor_sync(0xffffffffu, wsum, 16);
        wsum += __shfl_xor_sync(0xffffffffu, wsum, 8);
        if (lane == 0) s_red[warp] = wsum;
        __syncthreads();              // barrier D: s_logits/s_red + s_qb visible

        // private 1/tot: masked rows contribute exactly 1.0 each (exp(1e-9))
        float t0 = 0.f, t1 = 0.f, t2 = 0.f, t3 = 0.f;
#pragma unroll
        for (int w = 0; w < NWARPS; w += 4) {
            t0 += s_red[w]; t1 += s_red[w + 1]; t2 += s_red[w + 2]; t3 += s_red[w + 3];
        }
        const float inv = __frcp_rn((float)Lb + ((t0 + t1) + (t2 + t3)));

        // pipelined qw[b+GRID] partials — inside the slack window (D..E)
        if (bn < BB) {
            const float* qb = s_qb + qc * 32;
            float p0 = 0.f, p1 = 0.f, p2 = 0.f, p3 = 0.f;
#pragma unroll
            for (int i = 0; i < 32; i += 4) {
                p0 = fmaf(wreg[i],     qb[i],     p0);
                p1 = fmaf(wreg[i + 1], qb[i + 1], p1);
                p2 = fmaf(wreg[i + 2], qb[i + 2], p2);
                p3 = fmaf(wreg[i + 3], qb[i + 3], p3);
            }
            s_tmp[qc * 128 + h] = (p0 + p1) + (p2 + p3);
        }

        // ---- pass 2: out[h] = inv * sum_l w_l * hist[l][h] (SMEM only) ----
        float4 a4 = {0.f, 0.f, 0.f, 0.f};
        for (int l = warp; l < LL; l += NWARPS) {
            const float sc = (l < Lb) ? 1.0f : s_logits[l];
            float4 v = s4[l * 32 + lane];
            a4.x = fmaf(sc, v.x, a4.x);
            a4.y = fmaf(sc, v.y, a4.y);
            a4.z = fmaf(sc, v.z, a4.z);
            a4.w = fmaf(sc, v.w, a4.w);
        }
        a4.x *= inv; a4.y *= inv; a4.z *= inv; a4.w *= inv;
        ((float4*)s_part)[warp * 32 + lane] = a4;
        __syncthreads();              // barrier E: buf reads done + s_tmp visible

        // ---- final reduce: 128 threads, conflict-free scalar columns ----
        if (tid < HH) {
            float vsum = 0.f;
#pragma unroll
            for (int g = 0; g < NWARPS; ++g) vsum += s_part[g * HH + tid];
            out[(size_t)b * HH + tid] = vsum;
        }
    }
}

// ---------------------------------------------------------------------------
extern "C" void kernel_launch(void* const* d_in, const int* in_sizes, int n_in,
                              void* d_out, int out_size) {
    // Bind inputs BY ELEMENT COUNT (all distinct) — immune to ordering.
    const float* query = nullptr;   // 1048576
    const float* hist  = nullptr;   // 209715200
    const void*  hlen  = nullptr;   // 8192
    const float* W     = nullptr;   // 16384
    for (int i = 0; i < n_in; ++i) {
        switch (in_sizes[i]) {
            case BB * QQ:      query = (const float*)d_in[i]; break;
            case BB * LL * HH: hist  = (const float*)d_in[i]; break;
            case BB:           hlen  = d_in[i];               break;
            case QQ * HH:      W     = (const float*)d_in[i]; break;
            default: break;
        }
    }
    float* out = (float*)d_out;

    const int smem = 54308 * 4 + 64;   // 217296 B

    cudaFuncSetAttribute(attn_fused_kernel,
                         cudaFuncAttributeMaxDynamicSharedMemorySize, smem);

    attn_fused_kernel<<<GRID, NTHREADS, smem>>>(query, W, hist, hlen, out);
}

// round 17
// speedup vs baseline: 1.1441x; 1.1268x over previous
#include <cuda_runtime.h>
#include <cstdint>

#define BB 8192
#define LL 200
#define QQ 128
#define HH 128
#define GRID 148
#define NTHREADS 512
#define NWARPS 16

#define ROW_FLOATS (LL * HH)          // 25600
#define ROW_BYTES  (ROW_FLOATS * 4)   // 102400

__device__ float g_qw[BB * HH];       // qw = query @ W (4 MB, L2-resident)
__device__ int g_len_is64;

// ---------------------------------------------------------------------------
// PTX helpers
// ---------------------------------------------------------------------------
__device__ __forceinline__ uint32_t smem_u32(const void* p) {
    uint32_t a;
    asm("{ .reg .u64 t; cvta.to.shared.u64 t, %1; cvt.u32.u64 %0, t; }"
        : "=r"(a) : "l"(p));
    return a;
}
__device__ __forceinline__ void mbar_init(uint32_t mbar, uint32_t count) {
    asm volatile("mbarrier.init.shared.b64 [%0], %1;" :: "r"(mbar), "r"(count) : "memory");
}
__device__ __forceinline__ void mbar_expect_tx(uint32_t mbar, uint32_t bytes) {
    asm volatile("mbarrier.arrive.expect_tx.shared.b64 _, [%0], %1;"
                 :: "r"(mbar), "r"(bytes) : "memory");
}
__device__ __forceinline__ void bulk_g2s(uint32_t dst, const void* src,
                                         uint32_t bytes, uint32_t mbar) {
    asm volatile(
        "cp.async.bulk.shared::cta.global.mbarrier::complete_tx::bytes "
        "[%0], [%1], %2, [%3];"
        :: "r"(dst), "l"(src), "r"(bytes), "r"(mbar) : "memory");
}
__device__ __forceinline__ void mbar_wait(uint32_t mbar, uint32_t parity) {
    uint32_t done;
    asm volatile(
        "{\n .reg .pred p;\n"
        " mbarrier.try_wait.parity.acquire.cta.shared::cta.b64 p, [%1], %2, 0x989680;\n"
        " selp.b32 %0, 1, 0, p;\n}"
        : "=r"(done) : "r"(mbar), "r"(parity) : "memory");
    while (!done) {
        asm volatile(
            "{\n .reg .pred p;\n"
            " mbarrier.try_wait.parity.acquire.cta.shared::cta.b64 p, [%1], %2, 0x989680;\n"
            " selp.b32 %0, 1, 0, p;\n}"
            : "=r"(done) : "r"(mbar), "r"(parity) : "memory");
    }
}

// ---------------------------------------------------------------------------
// Kernel 1: qw = query @ W. 128 CTAs x 256 threads, 64 rows/CTA (R6 config).
// Fires PDL completion at the end.
// ---------------------------------------------------------------------------
__global__ __launch_bounds__(256, 2) void qw_gemm_kernel(
    const float* __restrict__ query, const float* __restrict__ W,
    const int* __restrict__ len32)
{
    extern __shared__ float smem1[];
    float* sW = smem1;                 // [128][128]
    float* sQ = smem1 + QQ * HH;       // [64][132] padded

    const int tid = threadIdx.x;
    const int b0  = blockIdx.x * 64;

    // len dtype detection: int64 values in [0,200) -> all odd dwords zero
    if (blockIdx.x == 0 && tid == 0) {
        int nz = 0;
#pragma unroll
        for (int i = 1; i < 256; i += 2) nz += (len32[i] != 0);
        g_len_is64 = (nz == 0) ? 1 : 0;
    }

    const float4* W4 = (const float4*)W;
    float4* sW4 = (float4*)sW;
#pragma unroll
    for (int i = 0; i < 16; ++i)
        sW4[tid + i * 256] = W4[tid + i * 256];

    const float4* Q4 = (const float4*)(query + (size_t)b0 * QQ);
#pragma unroll
    for (int i = 0; i < 8; ++i) {
        int idx = tid + i * 256;
        int r = idx >> 5;
        int c = (idx & 31) << 2;
        float4 v = Q4[idx];
        *(float4*)&sQ[r * 132 + c] = v;
    }
    __syncthreads();

    const int j  = tid & 15;
    const int i  = tid >> 4;
    const int r0 = i * 4;
    const int h0 = j * 8;

    float acc[4][8];
#pragma unroll
    for (int a = 0; a < 4; ++a)
#pragma unroll
        for (int c = 0; c < 8; ++c) acc[a][c] = 0.f;

#pragma unroll 4
    for (int q = 0; q < QQ; ++q) {
        float4 w0 = *(const float4*)&sW[q * HH + h0];
        float4 w1 = *(const float4*)&sW[q * HH + h0 + 4];
        float wv[8] = {w0.x, w0.y, w0.z, w0.w, w1.x, w1.y, w1.z, w1.w};
        float qv[4];
#pragma unroll
        for (int a = 0; a < 4; ++a) qv[a] = sQ[(r0 + a) * 132 + q];
#pragma unroll
        for (int a = 0; a < 4; ++a)
#pragma unroll
            for (int c = 0; c < 8; ++c)
                acc[a][c] = fmaf(qv[a], wv[c], acc[a][c]);
    }

#pragma unroll
    for (int a = 0; a < 4; ++a) {
        float4 o0 = {acc[a][0], acc[a][1], acc[a][2], acc[a][3]};
        float4 o1 = {acc[a][4], acc[a][5], acc[a][6], acc[a][7]};
        float* dst = g_qw + (size_t)(b0 + r0 + a) * HH + h0;
        *(float4*)dst       = o0;
        *(float4*)(dst + 4) = o1;
    }

    asm volatile("griddepcontrol.launch_dependents;");
}

// ---------------------------------------------------------------------------
// Kernel 2: persistent, double-buffered, SINGLE-PASS attention pooling.
// grid=148 (1 CTA/SM), 512 threads (16 warps).
//
// One traversal of hist per row: load v once, compute weight inline
// (1 for masked rows, exp(logit) otherwise — logit via 3-SHFL dot), and
// accumulate w*v in registers. Normalization (1/tot) applied only at the
// final STG. Pass-2 and s_logits are GONE; 2 barriers/row with a much
// shorter serial chain.
//
// SMEM (floats): buf0 [0,25600) | buf1 [25600,51200)
//   s_red [51200,51216) | s_part [51216,53264) (16x128) | mbar @ 53264
// ---------------------------------------------------------------------------
__global__ __launch_bounds__(NTHREADS, 1) void attn_pool_kernel(
    const float* __restrict__ hist, const void* __restrict__ hlen,
    float* __restrict__ out)
{
    extern __shared__ float smem[];
    float*  bufs[2] = { smem, smem + ROW_FLOATS };
    float*  s_red   = smem + 2 * ROW_FLOATS;           // 51200 (16 warp wsums)
    float*  s_part  = s_red + 16;                      // 51216 (16x128, 16B-aligned)
    uint64_t* mbar  = (uint64_t*)(smem + 53264);       // byte 213056, 8B aligned

    const int tid  = threadIdx.x;
    const int warp = tid >> 5;
    const int lane = tid & 31;
    const int bid  = blockIdx.x;
    const int k    = lane & 7;      // column octet (0..7)
    const int r    = lane >> 3;     // row-in-group (0..3)

    const uint32_t m0 = smem_u32(&mbar[0]);
    const uint32_t m1 = smem_u32(&mbar[1]);
    const uint32_t buf_a[2] = { smem_u32(bufs[0]), smem_u32(bufs[1]) };

    if (tid == 0) { mbar_init(m0, 1); mbar_init(m1, 1); }
    __syncthreads();

    // prologue: first row into buf0 (independent of gemm)
    if (tid == 0) {
        mbar_expect_tx(m0, ROW_BYTES);
        bulk_g2s(buf_a[0], hist + (size_t)bid * ROW_FLOATS, ROW_BYTES, m0);
    }

    // PDL: wait for gemm before touching g_qw / g_len_is64
    asm volatile("griddepcontrol.wait;" ::: "memory");
    const int is64 = g_len_is64;

    uint32_t ph0 = 0, ph1 = 0;
    int it = 0;
    for (int b = bid; b < BB; b += GRID, ++it) {
        const int cur = it & 1;

        // prefetch next row (its buffer's reads sealed by last iter's barrier 1)
        const int bn = b + GRID;
        if (bn < BB && tid == 0) {
            const uint32_t mb = cur ? m0 : m1;
            mbar_expect_tx(mb, ROW_BYTES);
            bulk_g2s(buf_a[cur ^ 1], hist + (size_t)bn * ROW_FLOATS, ROW_BYTES, mb);
        }

        // qw fragment + length while the copy runs
        const float4* qw4 = (const float4*)(g_qw + (size_t)b * HH);
        float4 qv[4];
#pragma unroll
        for (int c = 0; c < 4; ++c) qv[c] = qw4[c * 8 + k];

        int Lb;
        if (is64) Lb = (int)((const long long*)hlen)[b];
        else      Lb = ((const int*)hlen)[b];
        const int g0 = Lb >> 2;      // first group with any unmasked row

        // wait current buffer
        if (cur == 0) { mbar_wait(m0, ph0); ph0 ^= 1; }
        else          { mbar_wait(m1, ph1); ph1 ^= 1; }

        const float4* s4 = (const float4*)bufs[cur];

        // ---- single pass: acc[c] += w_l * v[c];  wsum += w_l (k==0) ----
        float4 acc0 = {0,0,0,0}, acc1 = {0,0,0,0}, acc2 = {0,0,0,0}, acc3 = {0,0,0,0};
        float wsum = 0.f;
        for (int g = warp; g < 50; g += NWARPS) {
            const int l = g * 4 + r;
            const float4* row4 = s4 + l * 32;
            float4 v0 = row4[k];
            float4 v1 = row4[8 + k];
            float4 v2 = row4[16 + k];
            float4 v3 = row4[24 + k];
            float w = 1.0f;                       // expf(1e-9f) == 1.0f
            if (g >= g0) {                        // warp-uniform branch
                float p = v0.x * qv[0].x + v0.y * qv[0].y + v0.z * qv[0].z + v0.w * qv[0].w
                        + v1.x * qv[1].x + v1.y * qv[1].y + v1.z * qv[1].z + v1.w * qv[1].w
                        + v2.x * qv[2].x + v2.y * qv[2].y + v2.z * qv[2].z + v2.w * qv[2].w
                        + v3.x * qv[3].x + v3.y * qv[3].y + v3.z * qv[3].z + v3.w * qv[3].w;
                p += __shfl_xor_sync(0xffffffffu, p, 4);
                p += __shfl_xor_sync(0xffffffffu, p, 2);
                p += __shfl_xor_sync(0xffffffffu, p, 1);
                if (l >= Lb) w = __expf(p);
            }
            acc0.x = fmaf(w, v0.x, acc0.x); acc0.y = fmaf(w, v0.y, acc0.y);
            acc0.z = fmaf(w, v0.z, acc0.z); acc0.w = fmaf(w, v0.w, acc0.w);
            acc1.x = fmaf(w, v1.x, acc1.x); acc1.y = fmaf(w, v1.y, acc1.y);
            acc1.z = fmaf(w, v1.z, acc1.z); acc1.w = fmaf(w, v1.w, acc1.w);
            acc2.x = fmaf(w, v2.x, acc2.x); acc2.y = fmaf(w, v2.y, acc2.y);
            acc2.z = fmaf(w, v2.z, acc2.z); acc2.w = fmaf(w, v2.w, acc2.w);
            acc3.x = fmaf(w, v3.x, acc3.x); acc3.y = fmaf(w, v3.y, acc3.y);
            acc3.z = fmaf(w, v3.z, acc3.z); acc3.w = fmaf(w, v3.w, acc3.w);
            if (k == 0) wsum += w;
        }

        // reduce across the 4 r-lanes (xor 8 then 16); all 16 components
#pragma unroll
        for (int s = 8; s <= 16; s += 8) {
            acc0.x += __shfl_xor_sync(0xffffffffu, acc0.x, s);
            acc0.y += __shfl_xor_sync(0xffffffffu, acc0.y, s);
            acc0.z += __shfl_xor_sync(0xffffffffu, acc0.z, s);
            acc0.w += __shfl_xor_sync(0xffffffffu, acc0.w, s);
            acc1.x += __shfl_xor_sync(0xffffffffu, acc1.x, s);
            acc1.y += __shfl_xor_sync(0xffffffffu, acc1.y, s);
            acc1.z += __shfl_xor_sync(0xffffffffu, acc1.z, s);
            acc1.w += __shfl_xor_sync(0xffffffffu, acc1.w, s);
            acc2.x += __shfl_xor_sync(0xffffffffu, acc2.x, s);
            acc2.y += __shfl_xor_sync(0xffffffffu, acc2.y, s);
            acc2.z += __shfl_xor_sync(0xffffffffu, acc2.z, s);
            acc2.w += __shfl_xor_sync(0xffffffffu, acc2.w, s);
            acc3.x += __shfl_xor_sync(0xffffffffu, acc3.x, s);
            acc3.y += __shfl_xor_sync(0xffffffffu, acc3.y, s);
            acc3.z += __shfl_xor_sync(0xffffffffu, acc3.z, s);
            acc3.w += __shfl_xor_sync(0xffffffffu, acc3.w, s);
            wsum   += __shfl_xor_sync(0xffffffffu, wsum,   s);
        }
        if (lane < 8) {
            float4* dst = (float4*)s_part + warp * 32;
            dst[lane]      = acc0;
            dst[8 + lane]  = acc1;
            dst[16 + lane] = acc2;
            dst[24 + lane] = acc3;
        }
        if (lane == 0) s_red[warp] = wsum;
        __syncthreads();             // barrier 1: s_part/s_red ready, buf reads done

        // ---- final reduce: 128 threads, conflict-free columns ----
        if (tid < HH) {
            float vsum = 0.f;
#pragma unroll
            for (int g = 0; g < NWARPS; ++g) vsum += s_part[g * HH + tid];
            float tot = 0.f;
#pragma unroll
            for (int g = 0; g < NWARPS; ++g) tot += s_red[g];
            out[(size_t)b * HH + tid] = vsum * __frcp_rn(tot);
        }
        __syncthreads();             // barrier 2: s_part/s_red reusable
    }
}

// ---------------------------------------------------------------------------
extern "C" void kernel_launch(void* const* d_in, const int* in_sizes, int n_in,
                              void* d_out, int out_size) {
    // Bind inputs BY ELEMENT COUNT (all distinct) — immune to ordering.
    const float* query = nullptr;   // 1048576
    const float* hist  = nullptr;   // 209715200
    const void*  hlen  = nullptr;   // 8192
    const float* W     = nullptr;   // 16384
    for (int i = 0; i < n_in; ++i) {
        switch (in_sizes[i]) {
            case BB * QQ:      query = (const float*)d_in[i]; break;
            case BB * LL * HH: hist  = (const float*)d_in[i]; break;
            case BB:           hlen  = d_in[i];               break;
            case QQ * HH:      W     = (const float*)d_in[i]; break;
            default: break;
        }
    }
    float* out = (float*)d_out;

    const int smem1 = (QQ * HH + 64 * 132) * (int)sizeof(float);   // 99328
    const int smem2 = 53264 * 4 + 64;                               // 213120

    cudaFuncSetAttribute(qw_gemm_kernel,
                         cudaFuncAttributeMaxDynamicSharedMemorySize, smem1);
    cudaFuncSetAttribute(attn_pool_kernel,
                         cudaFuncAttributeMaxDynamicSharedMemorySize, smem2);

    qw_gemm_kernel<<<BB / 64, 256, smem1>>>(query, W, (const int*)hlen);

    cudaLaunchConfig_t cfg = {};
    cfg.gridDim  = dim3(GRID, 1, 1);
    cfg.blockDim = dim3(NTHREADS, 1, 1);
    cfg.dynamicSmemBytes = smem2;
    cfg.stream = 0;
    cudaLaunchAttribute attr[1];
    attr[0].id = cudaLaunchAttributeProgrammaticStreamSerialization;
    attr[0].val.programmaticStreamSerializationAllowed = 1;
    cfg.attrs = attr;
    cfg.numAttrs = 1;
    cudaLaunchKernelEx(&cfg, attn_pool_kernel, hist, (const void*)hlen, out);
}